// round 10
// baseline (speedup 1.0000x reference)
#include <cuda_runtime.h>
#include <cstdint>

#define N_TOTAL 100000
#define DIM     128
#define N_USER  50000
#define M_ENT   50000
#define E_MAX   1700000
#define GEMM_BLOCKS_PER_ENT 391   // ceil(50000/128)

// Scratch (device globals)
__device__ float    g_li[(size_t)N_TOTAL * DIM];  // SpMM result (51.2 MB)
__device__ unsigned g_wt[2][DIM * DIM];           // W in TF32, fragment-permuted
__device__ int  g_cnt[N_TOTAL];                   // row degree
__device__ int  g_off[N_TOTAL];                   // row start
__device__ int  g_cur[N_TOTAL];                   // cursor
__device__ int2 g_edge[E_MAX];                    // (col, val_bits) row-sorted

__device__ __forceinline__ unsigned cvt_tf32(float f) {
    unsigned r;
    asm("cvt.rna.tf32.f32 %0, %1;" : "=r"(r) : "f"(f));
    return r;
}

// ---------------------------------------------------------------------------
// 0) zero row counters
// ---------------------------------------------------------------------------
__global__ void zero_cnt_kernel() {
    int i = blockIdx.x * blockDim.x + threadIdx.x;
    if (i < N_TOTAL) g_cnt[i] = 0;
}

// ---------------------------------------------------------------------------
// 1) histogram of destination rows (100k counters -> low contention)
// ---------------------------------------------------------------------------
__global__ void hist_kernel(const int* __restrict__ rows_u,
                            const int* __restrict__ rows_i,
                            int E_u, int E_i) {
    int e = blockIdx.x * blockDim.x + threadIdx.x;
    if (e < E_u) {
        atomicAdd(&g_cnt[__ldg(rows_u + e)], 1);
    } else {
        e -= E_u;
        if (e < E_i) atomicAdd(&g_cnt[N_USER + __ldg(rows_i + e)], 1);
    }
}

// ---------------------------------------------------------------------------
// 2) exclusive scan over 100k rows (one block)
// ---------------------------------------------------------------------------
#define SCAN_THREADS 1024
#define SCAN_CHUNK   98
__global__ void scan_kernel() {
    __shared__ int sums[SCAN_THREADS];
    int t = threadIdx.x;
    int lo = t * SCAN_CHUNK;
    int hi = min(lo + SCAN_CHUNK, N_TOTAL);

    int s = 0;
    for (int i = lo; i < hi; i++) s += g_cnt[i];
    sums[t] = s;
    __syncthreads();

    for (int d = 1; d < SCAN_THREADS; d <<= 1) {
        int v = (t >= d) ? sums[t - d] : 0;
        __syncthreads();
        sums[t] += v;
        __syncthreads();
    }
    int run = (t == 0) ? 0 : sums[t - 1];

    for (int i = lo; i < hi; i++) {
        g_off[i] = run;
        g_cur[i] = run;
        run += g_cnt[i];
    }
}

// ---------------------------------------------------------------------------
// 3) permute edges into row-sorted order (single STG.64 per edge)
// ---------------------------------------------------------------------------
__global__ void permute_kernel(const int*   __restrict__ rows_u,
                               const int*   __restrict__ cols_u,
                               const float* __restrict__ vals_u,
                               const int*   __restrict__ rows_i,
                               const int*   __restrict__ cols_i,
                               const float* __restrict__ vals_i,
                               int E_u, int E_i) {
    int e = blockIdx.x * blockDim.x + threadIdx.x;
    int r, c; float v;
    if (e < E_u) {
        r = __ldg(rows_u + e);
        c = __ldg(cols_u + e);
        v = __ldg(vals_u + e);
    } else {
        e -= E_u;
        if (e >= E_i) return;
        r = N_USER + __ldg(rows_i + e);
        c = __ldg(cols_i + e);
        v = __ldg(vals_i + e);
    }
    int pos = atomicAdd(&g_cur[r], 1);
    g_edge[pos] = make_int2(c, __float_as_int(v));
}

// ---------------------------------------------------------------------------
// 4) convert W to TF32, fragment-permuted: g_wt[e][k*128 + lq*16 + n]
// ---------------------------------------------------------------------------
__global__ void wconv_kernel(const float* __restrict__ Wu,
                             const float* __restrict__ Wi) {
    int i = blockIdx.x * blockDim.x + threadIdx.x;
    if (i < DIM * DIM) {
        int k = i >> 7, col = i & 127;
        int lq = col >> 4, n = col & 15;
        int src = k * DIM + n * 8 + lq;
        g_wt[0][i] = cvt_tf32(__ldg(Wu + src));
        g_wt[1][i] = cvt_tf32(__ldg(Wi + src));
    }
}

// ---------------------------------------------------------------------------
// 5) gather SpMM: one warp per row. Broadcast edge loads, 8 independent
//    gathers in flight, register accumulation, one coalesced store.
// ---------------------------------------------------------------------------
__global__ __launch_bounds__(256)
void spmm_kernel(const float* __restrict__ ebs) {
    int gwid = (blockIdx.x * blockDim.x + threadIdx.x) >> 5;
    int lane = threadIdx.x & 31;
    if (gwid >= N_TOTAL) return;

    int start = g_off[gwid];
    int cnt   = g_cnt[gwid];
    const int2* ep = g_edge + start;
    const float4* ebs4 = reinterpret_cast<const float4*>(ebs);

    float4 acc = make_float4(0.f, 0.f, 0.f, 0.f);

    for (int base = 0; base < cnt; base += 8) {
        int m = cnt - base;   // >=1
        int2 e[8];
        float4 gv[8];
#pragma unroll
        for (int j = 0; j < 8; j++)
            if (j < m) e[j] = __ldg(ep + base + j);     // broadcast (uniform addr)
#pragma unroll
        for (int j = 0; j < 8; j++)
            if (j < m) gv[j] = ebs4[(size_t)e[j].x * 32 + lane];  // independent LDGs
#pragma unroll
        for (int j = 0; j < 8; j++)
            if (j < m) {
                float v = __int_as_float(e[j].y);
                acc.x = fmaf(v, gv[j].x, acc.x);
                acc.y = fmaf(v, gv[j].y, acc.y);
                acc.z = fmaf(v, gv[j].z, acc.z);
                acc.w = fmaf(v, gv[j].w, acc.w);
            }
    }
    reinterpret_cast<float4*>(g_li)[(size_t)gwid * 32 + lane] = acc;
}

// ---------------------------------------------------------------------------
// 6) TF32 tensor-core GEMM + ReLU (unchanged R8 kernel: measured 42 us)
// ---------------------------------------------------------------------------
__global__ __launch_bounds__(256, 2)
void gemm_relu_tf32_kernel(float* __restrict__ out) {
    __shared__ unsigned Ws[DIM][132];
    __shared__ float    As[2][DIM][12];

    int b = blockIdx.x;
    int entity = (b >= GEMM_BLOCKS_PER_ENT) ? 1 : 0;
    int blockRow = (b - entity * GEMM_BLOCKS_PER_ENT) * 128;
    const float* A = g_li + (size_t)(entity ? N_USER : 0) * DIM;
    float* O = out + (size_t)(entity ? N_USER : 0) * DIM;

    int tid = threadIdx.x;

    {
        const uint4* s4 = reinterpret_cast<const uint4*>(g_wt[entity]);
#pragma unroll
        for (int i = 0; i < 16; i++) {
            int u = tid + i * 256;
            uint4 v = s4[u];
            int idx = u * 4;
            *reinterpret_cast<uint4*>(&Ws[idx >> 7][idx & 127]) = v;
        }
    }

    int arow = tid >> 1;
    int acg  = tid & 1;
    int agrow = blockRow + arow;
    bool avalid = (agrow < M_ENT);
    const float* aptr = A + (size_t)(avalid ? agrow : 0) * DIM + acg * 4;

    {
        float4 f = avalid ? *reinterpret_cast<const float4*>(aptr)
                          : make_float4(0.f, 0.f, 0.f, 0.f);
        *reinterpret_cast<float4*>(&As[0][arow][acg * 4]) = f;
    }
    __syncthreads();

    int warp = tid >> 5;
    int lane = tid & 31;
    int lq = lane >> 2;
    int lr = lane & 3;

    int rloc  = warp * 16 + lq;
    int rloc2 = rloc + 8;
    int row_a  = blockRow + rloc;
    int row_a2 = blockRow + rloc2;
    bool va  = row_a  < M_ENT;
    bool va2 = row_a2 < M_ENT;

    float acc[16][4];
#pragma unroll
    for (int n = 0; n < 16; n++)
#pragma unroll
        for (int j = 0; j < 4; j++) acc[n][j] = 0.f;

#pragma unroll 1
    for (int ks = 0; ks < 16; ks++) {
        int buf = ks & 1;

        float4 pf = make_float4(0.f, 0.f, 0.f, 0.f);
        if (ks < 15 && avalid)
            pf = *reinterpret_cast<const float4*>(aptr + (ks + 1) * 8);

        uint4 b0q[4], b1q[4];
        {
            const uint4* w0 = reinterpret_cast<const uint4*>(&Ws[ks * 8 + lr][lq * 16]);
            const uint4* w1 = reinterpret_cast<const uint4*>(&Ws[ks * 8 + 4 + lr][lq * 16]);
#pragma unroll
            for (int j = 0; j < 4; j++) { b0q[j] = w0[j]; b1q[j] = w1[j]; }
        }
        const unsigned* bw0 = reinterpret_cast<const unsigned*>(b0q);
        const unsigned* bw1 = reinterpret_cast<const unsigned*>(b1q);

        unsigned a0 = cvt_tf32(As[buf][rloc ][lr    ]);
        unsigned a1 = cvt_tf32(As[buf][rloc2][lr    ]);
        unsigned a2 = cvt_tf32(As[buf][rloc ][lr + 4]);
        unsigned a3 = cvt_tf32(As[buf][rloc2][lr + 4]);

#pragma unroll
        for (int n = 0; n < 16; n++) {
            asm volatile(
                "mma.sync.aligned.m16n8k8.row.col.f32.tf32.tf32.f32 "
                "{%0,%1,%2,%3}, {%4,%5,%6,%7}, {%8,%9}, {%0,%1,%2,%3};\n"
                : "+f"(acc[n][0]), "+f"(acc[n][1]), "+f"(acc[n][2]), "+f"(acc[n][3])
                : "r"(a0), "r"(a1), "r"(a2), "r"(a3), "r"(bw0[n]), "r"(bw1[n]));
        }

        if (ks < 15)
            *reinterpret_cast<float4*>(&As[buf ^ 1][arow][acg * 4]) = pf;
        __syncthreads();
    }

#pragma unroll
    for (int n = 0; n < 16; n++) {
        int col = n * 8 + lr * 2;
        if (va) {
            float2 o;
            o.x = fmaxf(acc[n][0], 0.f);
            o.y = fmaxf(acc[n][1], 0.f);
            *reinterpret_cast<float2*>(O + (size_t)row_a * DIM + col) = o;
        }
        if (va2) {
            float2 o;
            o.x = fmaxf(acc[n][2], 0.f);
            o.y = fmaxf(acc[n][3], 0.f);
            *reinterpret_cast<float2*>(O + (size_t)row_a2 * DIM + col) = o;
        }
    }
}

// ---------------------------------------------------------------------------
extern "C" void kernel_launch(void* const* d_in, const int* in_sizes, int n_in,
                              void* d_out, int out_size) {
    const float* ebs    = (const float*)d_in[0];
    const int*   rows_u = (const int*)  d_in[1];
    const int*   cols_u = (const int*)  d_in[2];
    const float* vals_u = (const float*)d_in[3];
    const float* W_u    = (const float*)d_in[4];
    const int*   rows_i = (const int*)  d_in[5];
    const int*   cols_i = (const int*)  d_in[6];
    const float* vals_i = (const float*)d_in[7];
    const float* W_i    = (const float*)d_in[8];
    float* out = (float*)d_out;

    int E_u = in_sizes[1];
    int E_i = in_sizes[5];
    int E_total = E_u + E_i;

    zero_cnt_kernel<<<(N_TOTAL + 255) / 256, 256>>>();
    hist_kernel<<<(E_total + 255) / 256, 256>>>(rows_u, rows_i, E_u, E_i);
    scan_kernel<<<1, SCAN_THREADS>>>();
    permute_kernel<<<(E_total + 255) / 256, 256>>>(rows_u, cols_u, vals_u,
                                                   rows_i, cols_i, vals_i,
                                                   E_u, E_i);
    wconv_kernel<<<(DIM * DIM + 255) / 256, 256>>>(W_u, W_i);
    spmm_kernel<<<(N_TOTAL * 32 + 255) / 256, 256>>>(ebs);
    gemm_relu_tf32_kernel<<<2 * GEMM_BLOCKS_PER_ENT, 256>>>(out);
}